// round 10
// baseline (speedup 1.0000x reference)
#include <cuda_runtime.h>
#include <cuda_bf16.h>

#define BN 8192
#define NB 64               // time buckets (time ~ U[0,1))
#define MARGIN 1.0f
#define TI 256              // i-rows (events) per block
#define TJ 64               // j entries per block tile
#define NJT (BN / TJ)       // 128 j-tiles
#define GX 32               // covers nc up to 8192
#define NBLK_MAIN (GX * NJT)
#define BIGF 1.2676506002282294e30f   // 2^100, exact power of two

// ---- allocation-free device state (zero-init at load; reset every call) ----
__device__ float    g_sum;
__device__ int      g_cnt;
__device__ unsigned g_tick_h;
__device__ unsigned g_tick_m;
__device__ int      cnt_all[NB], cnt_ev[NB];
__device__ int      fill_all[NB], fill_ev[NB];
__device__ int      off_all[NB + 1], off_ev[NB + 1];
__device__ float2   sj_sorted[BN];     // (t*2^100, -risk), bucket-sorted
__device__ float    e_pr[BN];          // MARGIN + risk_i   (events, bucket-sorted)
__device__ float    e_tB[BN];          // t_i * 2^100
__device__ int      e_jstart[BN];      // off_all[b_i + 1]  (monotone in index)
__device__ int      e_off[BN];         // off_all[b_i]      (monotone in index)

// ---- histogram (smem) + fused exclusive scan in the last block ----
__global__ void __launch_bounds__(1024)
k_hist(const float* __restrict__ timev, const int* __restrict__ event) {
    __shared__ int h_all[NB], h_ev[NB];
    __shared__ int s_last;
    const int tid = threadIdx.x;
    if (tid < NB) { h_all[tid] = 0; h_ev[tid] = 0; }
    __syncthreads();

    const int idx = blockIdx.x * 1024 + tid;          // 8 blocks x 1024 == BN
    const float t = timev[idx];
    const int b = min((int)(t * (float)NB), NB - 1);
    atomicAdd(&h_all[b], 1);
    if (event[idx] == 1) atomicAdd(&h_ev[b], 1);
    __syncthreads();

    if (tid < NB) {
        if (h_all[tid]) atomicAdd(&cnt_all[tid], h_all[tid]);
        if (h_ev[tid])  atomicAdd(&cnt_ev[tid],  h_ev[tid]);
    }
    __threadfence();
    __syncthreads();
    if (tid == 0) s_last = (atomicAdd(&g_tick_h, 1u) == gridDim.x - 1) ? 1 : 0;
    __syncthreads();

    if (s_last) {   // last block: all histograms are in L2; do the scan here
        if (tid < NB) {
            h_all[tid] = atomicAdd(&cnt_all[tid], 0);
            h_ev[tid]  = atomicAdd(&cnt_ev[tid], 0);
        }
        __syncthreads();
        for (int st = 1; st < NB; st <<= 1) {         // Hillis-Steele inclusive
            int va = 0, ve = 0;
            if (tid < NB && tid >= st) { va = h_all[tid - st]; ve = h_ev[tid - st]; }
            __syncthreads();
            if (tid < NB) { h_all[tid] += va; h_ev[tid] += ve; }
            __syncthreads();
        }
        if (tid < NB) { off_all[tid + 1] = h_all[tid]; off_ev[tid + 1] = h_ev[tid]; }
        if (tid == 0) { off_all[0] = 0; off_ev[0] = 0; g_tick_h = 0u; }
    }
}

// ---- scatter into bucket-sorted order ----
__global__ void __launch_bounds__(1024)
k_scatter(const float* __restrict__ risk, const float* __restrict__ timev,
          const int* __restrict__ event) {
    const int idx = blockIdx.x * 1024 + threadIdx.x;
    const float t = timev[idx], r = risk[idx];
    const int b = min((int)(t * (float)NB), NB - 1);
    const int pos = off_all[b] + atomicAdd(&fill_all[b], 1);
    sj_sorted[pos] = make_float2(t * BIGF, -r);
    if (event[idx] == 1) {
        const int ep = off_ev[b] + atomicAdd(&fill_ev[b], 1);
        e_pr[ep]     = MARGIN + r;
        e_tB[ep]     = t * BIGF;
        e_jstart[ep] = off_all[b + 1];
        e_off[ep]    = off_all[b];
    }
}

// ---- main pairwise kernel: one (i-block, j-tile) per CTA ----
__global__ void __launch_bounds__(TI)
k_main(float* __restrict__ out) {
    __shared__ __align__(16) float4 sj4[TJ / 2];   // (tB0,tB1,-r0,-r1) per group
    __shared__ float ws[TI / 32], wc[TI / 32];

    const int nc = off_ev[NB];
    const int i0 = blockIdx.x * TI;
    const int jb = blockIdx.y * TJ;

    bool dowork = false;
    int  jmaxstart = 0;
    if (i0 < nc) {
        const int ilast = min(nc, i0 + TI) - 1;
        const int jminoff = e_off[i0];             // smallest bucket start in block
        jmaxstart = e_jstart[ilast];               // largest jstart in block
        dowork = (jb + TJ > jminoff);              // not entirely below all buckets
    }

    if (dowork) {
        if (threadIdx.x < TJ) {                    // stage tile
            float2 p = sj_sorted[jb + threadIdx.x];
            float* st = reinterpret_cast<float*>(sj4);
            const int g = threadIdx.x >> 1, o = threadIdx.x & 1;
            st[g * 4 + o]     = p.x;
            st[g * 4 + 2 + o] = p.y;
        }
        __syncthreads();

        const int  i     = i0 + threadIdx.x;
        const bool valid = i < nc;
        const float pr   = valid ? e_pr[i] : -1e30f;

        float s0 = 0.f, s1 = 0.f, s2 = 0.f, s3 = 0.f;
        float ssum, csum;

        if (jb >= jmaxstart) {
            // Mask-free: every pair valid (bucket_j > b_i for all threads).
            #pragma unroll 8
            for (int g = 0; g < TJ / 2; ++g) {
                float4 v = sj4[g];
                float h0 = fmaxf(pr + v.z, 0.0f);
                float h1 = fmaxf(pr + v.w, 0.0f);
                if (g & 1) { s2 += h0; s3 += h1; }
                else       { s0 += h0; s1 += h1; }
            }
            ssum = (s0 + s1) + (s2 + s3);
            csum = valid ? (float)TJ : 0.0f;       // all TJ pairs count
        } else {
            // Straddle: exact arithmetic mask (dtB is 0 or |dtB| >= 2^77 >> hinge)
            const float tbB = valid ? e_tB[i] : BIGF;
            float c0 = 0.f, c1 = 0.f;
            #pragma unroll 8
            for (int g = 0; g < TJ / 2; ++g) {
                float4 v = sj4[g];
                float dt0 = v.x - tbB, dt1 = v.y - tbB;
                float d0 = pr + v.z,  d1 = pr + v.w;
                s0 += fmaxf(fminf(dt0, d0), 0.0f);
                s1 += fmaxf(fminf(dt1, d1), 0.0f);
                c0 += __saturatef(dt0);            // exact {0,1}
                c1 += __saturatef(dt1);
            }
            ssum = s0 + s1;
            csum = c0 + c1;
        }

        // block reduce
        #pragma unroll
        for (int o = 16; o > 0; o >>= 1) {
            ssum += __shfl_down_sync(0xFFFFFFFFu, ssum, o);
            csum += __shfl_down_sync(0xFFFFFFFFu, csum, o);
        }
        const int w = threadIdx.x >> 5, l = threadIdx.x & 31;
        if (l == 0) { ws[w] = ssum; wc[w] = csum; }
        __syncthreads();
        if (w == 0) {
            ssum = (l < TI / 32) ? ws[l] : 0.0f;
            csum = (l < TI / 32) ? wc[l] : 0.0f;
            #pragma unroll
            for (int o = (TI / 64); o > 0; o >>= 1) {
                ssum += __shfl_down_sync(0xFFFFFFFFu, ssum, o);
                csum += __shfl_down_sync(0xFFFFFFFFu, csum, o);
            }
            if (l == 0) {
                atomicAdd(&g_sum, ssum);
                atomicAdd(&g_cnt, __float2int_rn(csum));   // <= 16384/block: exact
            }
        }
    }

    // Ticket: last of all NBLK_MAIN blocks finalizes and resets state.
    if (threadIdx.x == 0) {
        __threadfence();
        unsigned old = atomicAdd(&g_tick_m, 1u);
        if (old == NBLK_MAIN - 1) {
            float sum = atomicAdd(&g_sum, 0.0f);
            int   cnt = atomicAdd(&g_cnt, 0);
            out[0] = (cnt == 0) ? 0.0f : sum / (float)cnt;
            g_sum = 0.0f; g_cnt = 0; g_tick_m = 0u;
            for (int k = 0; k < NB; ++k) {
                cnt_all[k] = 0; cnt_ev[k] = 0;
                fill_all[k] = 0; fill_ev[k] = 0;
            }
            __threadfence();
        }
    }
}

extern "C" void kernel_launch(void* const* d_in, const int* in_sizes, int n_in,
                              void* d_out, int out_size) {
    // metadata order: z (unused), risk, time, event
    const float* risk  = (const float*)d_in[1];
    const float* timev = (const float*)d_in[2];
    const int*   event = (const int*)d_in[3];
    float* out = (float*)d_out;

    k_hist   <<<BN / 1024, 1024>>>(timev, event);
    k_scatter<<<BN / 1024, 1024>>>(risk, timev, event);
    dim3 grid(GX, NJT);
    k_main   <<<grid, TI>>>(out);
}